// round 1
// baseline (speedup 1.0000x reference)
#include <cuda_runtime.h>

// StateIntegratorND: UT sigma-point propagation through a 20->128->128->16 tanh MLP
// integrated with fixed-step dopri5 (4 substeps), then weighted mean over S=41.
//
// Strategy: warp handles 4 points; all weights in shared memory; fp32 FFMA
// throughout; tanh.approx.f32 for activations; two-kernel (integrate + reduce).

#define HS 0.0025f   // DT / N_STEPS = 0.01 / 4

// scratch for per-point weighted end states (B=1024, S=41, NX=16)
__device__ float g_scratch[1024 * 41 * 16];

__device__ __forceinline__ float tanh_fast(float x) {
    float y;
    asm("tanh.approx.f32 %0, %1;" : "=f"(y) : "f"(x));
    return y;
}

__device__ __forceinline__ void tanh4(float4& v) {
    v.x = tanh_fast(v.x); v.y = tanh_fast(v.y);
    v.z = tanh_fast(v.z); v.w = tanh_fast(v.w);
}

// ---- shared memory layout (in floats) ----
#define SW1   0              // W1 [20][128]
#define SB1   2560           // b1 [128]
#define SW2   2688           // W2 [128][128]
#define SB2   19072          // b2 [128]
#define SW3   19200          // W3 transposed [16][129] (pad for bank spread)
#define SB3   21264          // b3 [16]
#define SWARP 21280          // per-warp staging
#define WSZ   1056           // per warp: h[4][128]=512, x0[4][16]=64, k[4][6][16]=384, cur[4][20]=80 -> 1040, pad
#define SMEM_FLOATS (SWARP + 16 * WSZ)   // 38176 floats = 152704 bytes

// One MLP evaluation f(cur) for 4 points, result -> kb[p][sidx][0..15]
__device__ __forceinline__ void eval_f(const float* __restrict__ sm,
                                       float* __restrict__ hb,
                                       const float* __restrict__ cur,
                                       float* __restrict__ kb,
                                       int lane, int sidx)
{
    // ---------- layer 1: 20 -> 128, tanh ----------
    {
        float4 bb = *(const float4*)(sm + SB1 + 4 * lane);
        float4 a0 = bb, a1 = bb, a2 = bb, a3 = bb;
        #pragma unroll
        for (int d = 0; d < 20; d++) {
            float4 w = *(const float4*)(sm + SW1 + d * 128 + 4 * lane);
            float c0 = cur[0 * 20 + d], c1 = cur[1 * 20 + d];
            float c2 = cur[2 * 20 + d], c3 = cur[3 * 20 + d];
            a0.x += c0 * w.x; a0.y += c0 * w.y; a0.z += c0 * w.z; a0.w += c0 * w.w;
            a1.x += c1 * w.x; a1.y += c1 * w.y; a1.z += c1 * w.z; a1.w += c1 * w.w;
            a2.x += c2 * w.x; a2.y += c2 * w.y; a2.z += c2 * w.z; a2.w += c2 * w.w;
            a3.x += c3 * w.x; a3.y += c3 * w.y; a3.z += c3 * w.z; a3.w += c3 * w.w;
        }
        tanh4(a0); tanh4(a1); tanh4(a2); tanh4(a3);
        ((float4*)(hb + 0 * 128))[lane] = a0;
        ((float4*)(hb + 1 * 128))[lane] = a1;
        ((float4*)(hb + 2 * 128))[lane] = a2;
        ((float4*)(hb + 3 * 128))[lane] = a3;
    }
    __syncwarp();

    // ---------- layer 2: 128 -> 128, tanh ----------
    {
        float4 bb = *(const float4*)(sm + SB2 + 4 * lane);
        float4 c0 = bb, c1 = bb, c2 = bb, c3 = bb;
        #pragma unroll 8
        for (int jq = 0; jq < 32; jq++) {
            float4 h0 = ((const float4*)(hb + 0 * 128))[jq];
            float4 h1 = ((const float4*)(hb + 1 * 128))[jq];
            float4 h2 = ((const float4*)(hb + 2 * 128))[jq];
            float4 h3 = ((const float4*)(hb + 3 * 128))[jq];
            const float* wr = sm + SW2 + (jq * 4) * 128 + 4 * lane;
            float4 w;
            w = *(const float4*)(wr);
            c0.x += h0.x * w.x; c0.y += h0.x * w.y; c0.z += h0.x * w.z; c0.w += h0.x * w.w;
            c1.x += h1.x * w.x; c1.y += h1.x * w.y; c1.z += h1.x * w.z; c1.w += h1.x * w.w;
            c2.x += h2.x * w.x; c2.y += h2.x * w.y; c2.z += h2.x * w.z; c2.w += h2.x * w.w;
            c3.x += h3.x * w.x; c3.y += h3.x * w.y; c3.z += h3.x * w.z; c3.w += h3.x * w.w;
            w = *(const float4*)(wr + 128);
            c0.x += h0.y * w.x; c0.y += h0.y * w.y; c0.z += h0.y * w.z; c0.w += h0.y * w.w;
            c1.x += h1.y * w.x; c1.y += h1.y * w.y; c1.z += h1.y * w.z; c1.w += h1.y * w.w;
            c2.x += h2.y * w.x; c2.y += h2.y * w.y; c2.z += h2.y * w.z; c2.w += h2.y * w.w;
            c3.x += h3.y * w.x; c3.y += h3.y * w.y; c3.z += h3.y * w.z; c3.w += h3.y * w.w;
            w = *(const float4*)(wr + 256);
            c0.x += h0.z * w.x; c0.y += h0.z * w.y; c0.z += h0.z * w.z; c0.w += h0.z * w.w;
            c1.x += h1.z * w.x; c1.y += h1.z * w.y; c1.z += h1.z * w.z; c1.w += h1.z * w.w;
            c2.x += h2.z * w.x; c2.y += h2.z * w.y; c2.z += h2.z * w.z; c2.w += h2.z * w.w;
            c3.x += h3.z * w.x; c3.y += h3.z * w.y; c3.z += h3.z * w.z; c3.w += h3.z * w.w;
            w = *(const float4*)(wr + 384);
            c0.x += h0.w * w.x; c0.y += h0.w * w.y; c0.z += h0.w * w.z; c0.w += h0.w * w.w;
            c1.x += h1.w * w.x; c1.y += h1.w * w.y; c1.z += h1.w * w.z; c1.w += h1.w * w.w;
            c2.x += h2.w * w.x; c2.y += h2.w * w.y; c2.z += h2.w * w.z; c2.w += h2.w * w.w;
            c3.x += h3.w * w.x; c3.y += h3.w * w.y; c3.z += h3.w * w.z; c3.w += h3.w * w.w;
        }
        tanh4(c0); tanh4(c1); tanh4(c2); tanh4(c3);
        __syncwarp();   // everyone done reading layer-1 h before overwrite
        ((float4*)(hb + 0 * 128))[lane] = c0;
        ((float4*)(hb + 1 * 128))[lane] = c1;
        ((float4*)(hb + 2 * 128))[lane] = c2;
        ((float4*)(hb + 3 * 128))[lane] = c3;
    }
    __syncwarp();

    // ---------- layer 3: 128 -> 16 ----------
    {
        int o = lane & 15, part = lane >> 4;
        float binit = sm[SB3 + o];
        float s0 = part ? 0.f : binit;
        float s1 = s0, s2 = s0, s3 = s0;
        const float* w3r = sm + SW3 + o * 129 + part * 64;
        const float* h0p = hb + 0 * 128 + part * 64;
        const float* h1p = hb + 1 * 128 + part * 64;
        const float* h2p = hb + 2 * 128 + part * 64;
        const float* h3p = hb + 3 * 128 + part * 64;
        #pragma unroll 8
        for (int j = 0; j < 64; j++) {
            float w = w3r[j];
            s0 += h0p[j] * w;
            s1 += h1p[j] * w;
            s2 += h2p[j] * w;
            s3 += h3p[j] * w;
        }
        s0 += __shfl_xor_sync(0xffffffffu, s0, 16);
        s1 += __shfl_xor_sync(0xffffffffu, s1, 16);
        s2 += __shfl_xor_sync(0xffffffffu, s2, 16);
        s3 += __shfl_xor_sync(0xffffffffu, s3, 16);
        if (lane < 16) {
            kb[0 * 96 + sidx * 16 + lane] = s0;
            kb[1 * 96 + sidx * 16 + lane] = s1;
            kb[2 * 96 + sidx * 16 + lane] = s2;
            kb[3 * 96 + sidx * 16 + lane] = s3;
        }
    }
    __syncwarp();
}

__global__ void __launch_bounds__(512, 1)
integ_kernel(const float* __restrict__ sp, const float* __restrict__ wp,
             const float* __restrict__ W1, const float* __restrict__ b1,
             const float* __restrict__ W2, const float* __restrict__ b2,
             const float* __restrict__ W3, const float* __restrict__ b3,
             int npoints)
{
    extern __shared__ float sm[];
    int tid = threadIdx.x;
    for (int i = tid; i < 2560;  i += 512) sm[SW1 + i] = W1[i];
    for (int i = tid; i < 128;   i += 512) sm[SB1 + i] = b1[i];
    for (int i = tid; i < 16384; i += 512) sm[SW2 + i] = W2[i];
    for (int i = tid; i < 128;   i += 512) sm[SB2 + i] = b2[i];
    for (int i = tid; i < 2048;  i += 512) { int j = i >> 4, o = i & 15; sm[SW3 + o * 129 + j] = W3[i]; }
    for (int i = tid; i < 16;    i += 512) sm[SB3 + i] = b3[i];
    __syncthreads();

    int warp = tid >> 5, lane = tid & 31;
    float* ws  = sm + SWARP + warp * WSZ;
    float* hb  = ws;          // [4][128]
    float* x0  = ws + 512;    // [4][16]
    float* kb  = ws + 576;    // [4][6][16]
    float* cur = ws + 960;    // [4][20]

    int base = (blockIdx.x * 16 + warp) * 4;

    #pragma unroll
    for (int p = 0; p < 4; p++) {
        int pt = base + p;
        float v = 0.f;
        if (pt < npoints && lane < 20) v = sp[pt * 20 + lane];
        if (lane < 20) cur[p * 20 + lane] = v;
        if (lane < 16) x0[p * 16 + lane] = v;
    }
    __syncwarp();

    const float A21 = 0.2f;
    const float A31 = 3.f / 40.f, A32 = 9.f / 40.f;
    const float A41 = 44.f / 45.f, A42 = -56.f / 15.f, A43 = 32.f / 9.f;
    const float A51 = 19372.f / 6561.f, A52 = -25360.f / 2187.f,
                A53 = 64448.f / 6561.f, A54 = -212.f / 729.f;
    const float A61 = 9017.f / 3168.f, A62 = -355.f / 33.f, A63 = 46732.f / 5247.f,
                A64 = 49.f / 176.f, A65 = -5103.f / 18656.f;
    const float Bc1 = 35.f / 384.f, Bc3 = 500.f / 1113.f, Bc4 = 125.f / 192.f,
                Bc5 = -2187.f / 6784.f, Bc6 = 11.f / 84.f;

    for (int step = 0; step < 4; step++) {
        eval_f(sm, hb, cur, kb, lane, 0);
        if (lane < 16) {
            #pragma unroll
            for (int p = 0; p < 4; p++) {
                const float* kp = kb + p * 96;
                cur[p * 20 + lane] = x0[p * 16 + lane] + HS * (A21 * kp[0 * 16 + lane]);
            }
        }
        __syncwarp();

        eval_f(sm, hb, cur, kb, lane, 1);
        if (lane < 16) {
            #pragma unroll
            for (int p = 0; p < 4; p++) {
                const float* kp = kb + p * 96;
                cur[p * 20 + lane] = x0[p * 16 + lane]
                    + HS * (A31 * kp[0 * 16 + lane] + A32 * kp[1 * 16 + lane]);
            }
        }
        __syncwarp();

        eval_f(sm, hb, cur, kb, lane, 2);
        if (lane < 16) {
            #pragma unroll
            for (int p = 0; p < 4; p++) {
                const float* kp = kb + p * 96;
                cur[p * 20 + lane] = x0[p * 16 + lane]
                    + HS * (A41 * kp[0 * 16 + lane] + A42 * kp[1 * 16 + lane]
                          + A43 * kp[2 * 16 + lane]);
            }
        }
        __syncwarp();

        eval_f(sm, hb, cur, kb, lane, 3);
        if (lane < 16) {
            #pragma unroll
            for (int p = 0; p < 4; p++) {
                const float* kp = kb + p * 96;
                cur[p * 20 + lane] = x0[p * 16 + lane]
                    + HS * (A51 * kp[0 * 16 + lane] + A52 * kp[1 * 16 + lane]
                          + A53 * kp[2 * 16 + lane] + A54 * kp[3 * 16 + lane]);
            }
        }
        __syncwarp();

        eval_f(sm, hb, cur, kb, lane, 4);
        if (lane < 16) {
            #pragma unroll
            for (int p = 0; p < 4; p++) {
                const float* kp = kb + p * 96;
                cur[p * 20 + lane] = x0[p * 16 + lane]
                    + HS * (A61 * kp[0 * 16 + lane] + A62 * kp[1 * 16 + lane]
                          + A63 * kp[2 * 16 + lane] + A64 * kp[3 * 16 + lane]
                          + A65 * kp[4 * 16 + lane]);
            }
        }
        __syncwarp();

        eval_f(sm, hb, cur, kb, lane, 5);
        if (lane < 16) {
            #pragma unroll
            for (int p = 0; p < 4; p++) {
                const float* kp = kb + p * 96;
                float xn = x0[p * 16 + lane]
                    + HS * (Bc1 * kp[0 * 16 + lane] + Bc3 * kp[2 * 16 + lane]
                          + Bc4 * kp[3 * 16 + lane] + Bc5 * kp[4 * 16 + lane]
                          + Bc6 * kp[5 * 16 + lane]);
                x0[p * 16 + lane] = xn;
                cur[p * 20 + lane] = xn;
            }
        }
        __syncwarp();
    }

    if (lane < 16) {
        #pragma unroll
        for (int p = 0; p < 4; p++) {
            int pt = base + p;
            if (pt < npoints)
                g_scratch[pt * 16 + lane] = wp[pt] * x0[p * 16 + lane];
        }
    }
}

__global__ void reduce_kernel(float* __restrict__ out, int B)
{
    int t = blockIdx.x * blockDim.x + threadIdx.x;
    if (t >= B * 16) return;
    int b = t >> 4, o = t & 15;
    const float* src = g_scratch + (b * 41) * 16 + o;
    float s = 0.f;
    #pragma unroll
    for (int j = 0; j < 41; j++) s += src[j * 16];
    out[t] = s;
}

extern "C" void kernel_launch(void* const* d_in, const int* in_sizes, int n_in,
                              void* d_out, int out_size)
{
    const float* sp = (const float*)d_in[0];
    const float* wp = (const float*)d_in[1];
    const float* W1 = (const float*)d_in[2];
    const float* b1 = (const float*)d_in[3];
    const float* W2 = (const float*)d_in[4];
    const float* b2 = (const float*)d_in[5];
    const float* W3 = (const float*)d_in[6];
    const float* b3 = (const float*)d_in[7];
    float* out = (float*)d_out;

    int npoints = in_sizes[0] / 20;          // B * 41
    if (npoints > 1024 * 41) npoints = 1024 * 41;
    int B = npoints / 41;

    int nblocks = (npoints + 63) / 64;       // 16 warps/block * 4 points/warp
    size_t smem = SMEM_FLOATS * sizeof(float);
    cudaFuncSetAttribute(integ_kernel, cudaFuncAttributeMaxDynamicSharedMemorySize, (int)smem);
    integ_kernel<<<nblocks, 512, smem>>>(sp, wp, W1, b1, W2, b2, W3, b3, npoints);

    int nthr = B * 16;
    reduce_kernel<<<(nthr + 255) / 256, 256>>>(out, B);
}

// round 3
// speedup vs baseline: 3.3912x; 3.3912x over previous
#include <cuda_runtime.h>
#include <cuda_bf16.h>
#include <cstdint>

// StateIntegratorND via warp-level bf16 mma.sync (base ISA, works on compute_103):
// - warp owns 16 sigma points (one m16 tile); all activations stay in registers
//   using the C-fragment == A-fragment layout identity (m16n8 C pair -> m16k16 A).
// - weights pre-packed into smem in B-fragment order (1 LDS.64 per frag/thread).
// - b1 folded into K as a ones-column; b2/b3 added in epilogues.
// - dopri5 (4 substeps) state fp32 in registers; no inter-warp syncs after staging.

#define HS 0.0025f   // DT / N_STEPS

__device__ float g_scratch[1024 * 41 * 16];

__device__ __forceinline__ float tanh_fast(float x) {
    float y; asm("tanh.approx.f32 %0, %1;" : "=f"(y) : "f"(x)); return y;
}
// pack two fp32 -> bf16x2 (lo = first elem, hi = second)
__device__ __forceinline__ uint32_t pack_bf16(float lo, float hi) {
    uint32_t r; asm("cvt.rn.bf16x2.f32 %0, %1, %2;" : "=r"(r) : "f"(hi), "f"(lo)); return r;
}

__device__ __forceinline__ void mma_bf16(float* c, const uint32_t* a, uint2 b) {
    asm volatile(
        "mma.sync.aligned.m16n8k16.row.col.f32.bf16.bf16.f32 "
        "{%0,%1,%2,%3}, {%4,%5,%6,%7}, {%8,%9}, {%0,%1,%2,%3};"
        : "+f"(c[0]), "+f"(c[1]), "+f"(c[2]), "+f"(c[3])
        : "r"(a[0]), "r"(a[1]), "r"(a[2]), "r"(a[3]), "r"(b.x), "r"(b.y));
}

// One MLP eval for the warp's 16 points.
// a1  : A-frag chunk0 (state x, cols 0-15)
// au  : A-frag chunk1 (u, bias-one, pad; cols 16-31) -- constant per point
// out : kk[8] = k-vector fragment (tile0 c0..c3, tile1 c0..c3)
__device__ __forceinline__ void eval_f(
    float kk[8], const uint32_t a1[4], const uint32_t au[4],
    const uint2* __restrict__ w1f,   // [2][16][32]
    const uint2* __restrict__ w2f,   // [8][16][32]
    const uint2* __restrict__ w3f,   // [8][2][32]
    const float* __restrict__ b2s,   // [128]
    const float* __restrict__ b3v,   // [4] per-thread b3 frag values
    int lane, int tig)
{
    float h[64];
    uint32_t A2[32];

    // ---------------- layer 1: K=32 (2 chunks), N=128 (16 tiles) ----------------
#pragma unroll
    for (int i = 0; i < 64; i++) h[i] = 0.f;
#pragma unroll
    for (int nt = 0; nt < 16; nt++) {
        mma_bf16(h + nt * 4, a1, w1f[(0 * 16 + nt) * 32 + lane]);
        mma_bf16(h + nt * 4, au, w1f[(1 * 16 + nt) * 32 + lane]);
    }
    // tanh -> A fragments for layer 2 (b1 already folded via ones-column)
#pragma unroll
    for (int c = 0; c < 8; c++) {
        const float* t = h + 8 * c;
        A2[c * 4 + 0] = pack_bf16(tanh_fast(t[0]), tanh_fast(t[1]));
        A2[c * 4 + 1] = pack_bf16(tanh_fast(t[2]), tanh_fast(t[3]));
        A2[c * 4 + 2] = pack_bf16(tanh_fast(t[4]), tanh_fast(t[5]));
        A2[c * 4 + 3] = pack_bf16(tanh_fast(t[6]), tanh_fast(t[7]));
    }

    // ---------------- layer 2: K=128 (8 chunks), N=128 (16 tiles) ----------------
#pragma unroll
    for (int i = 0; i < 64; i++) h[i] = 0.f;
#pragma unroll
    for (int nt = 0; nt < 16; nt++) {
#pragma unroll
        for (int kc = 0; kc < 8; kc++)
            mma_bf16(h + nt * 4, A2 + kc * 4, w2f[(kc * 16 + nt) * 32 + lane]);
    }
    // + b2, tanh -> A fragments for layer 3
#pragma unroll
    for (int c = 0; c < 8; c++) {
        float2 bA = *(const float2*)&b2s[(2 * c) * 8 + 2 * tig];
        float2 bB = *(const float2*)&b2s[(2 * c + 1) * 8 + 2 * tig];
        const float* t = h + 8 * c;
        A2[c * 4 + 0] = pack_bf16(tanh_fast(t[0] + bA.x), tanh_fast(t[1] + bA.y));
        A2[c * 4 + 1] = pack_bf16(tanh_fast(t[2] + bA.x), tanh_fast(t[3] + bA.y));
        A2[c * 4 + 2] = pack_bf16(tanh_fast(t[4] + bB.x), tanh_fast(t[5] + bB.y));
        A2[c * 4 + 3] = pack_bf16(tanh_fast(t[6] + bB.x), tanh_fast(t[7] + bB.y));
    }

    // ---------------- layer 3: K=128 (8 chunks), N=16 (2 tiles) ----------------
    kk[0] = b3v[0]; kk[1] = b3v[1]; kk[2] = b3v[0]; kk[3] = b3v[1];
    kk[4] = b3v[2]; kk[5] = b3v[3]; kk[6] = b3v[2]; kk[7] = b3v[3];
#pragma unroll
    for (int kc = 0; kc < 8; kc++) {
        mma_bf16(kk + 0, A2 + kc * 4, w3f[(kc * 2 + 0) * 32 + lane]);
        mma_bf16(kk + 4, A2 + kc * 4, w3f[(kc * 2 + 1) * 32 + lane]);
    }
}

__global__ void __launch_bounds__(128, 2)
integ_kernel(const float* __restrict__ sp, const float* __restrict__ wp,
             const float* __restrict__ W1, const float* __restrict__ b1,
             const float* __restrict__ W2, const float* __restrict__ b2,
             const float* __restrict__ W3, const float* __restrict__ b3,
             int npoints)
{
    // fragment-ordered weight storage
    __shared__ uint2 w1f[2 * 16 * 32];   //  8 KB
    __shared__ uint2 w2f[8 * 16 * 32];   // 32 KB
    __shared__ uint2 w3f[8 * 2 * 32];    //  4 KB
    __shared__ float b2s[128];

    const int tid = threadIdx.x;
    const int warp = tid >> 5, lane = tid & 31;
    const int tig = lane & 3, grp = lane >> 2;

    // ---- stage weights as B fragments ----
    // elem e of frag (kc,nt,lane): krow = kc*16 + (e<2 ? 2*tig+e : 8+2*tig+(e-2)), n = nt*8+grp
    {
        __nv_bfloat16* p = (__nv_bfloat16*)w1f;
        for (int i = tid; i < 2 * 16 * 32 * 4; i += 128) {
            int e = i & 3, ln = (i >> 2) & 31, nt = (i >> 7) & 15, kc = i >> 11;
            int tg = ln & 3, gd = ln >> 2;
            int krow = kc * 16 + ((e < 2) ? (2 * tg + e) : (8 + 2 * tg + (e - 2)));
            int n = nt * 8 + gd;
            float v = (krow < 20) ? W1[krow * 128 + n] : ((krow == 20) ? b1[n] : 0.f);
            p[i] = __float2bfloat16(v);
        }
        p = (__nv_bfloat16*)w2f;
        for (int i = tid; i < 8 * 16 * 32 * 4; i += 128) {
            int e = i & 3, ln = (i >> 2) & 31, nt = (i >> 7) & 15, kc = i >> 11;
            int tg = ln & 3, gd = ln >> 2;
            int krow = kc * 16 + ((e < 2) ? (2 * tg + e) : (8 + 2 * tg + (e - 2)));
            int n = nt * 8 + gd;
            p[i] = __float2bfloat16(W2[krow * 128 + n]);
        }
        p = (__nv_bfloat16*)w3f;
        for (int i = tid; i < 8 * 2 * 32 * 4; i += 128) {
            int e = i & 3, ln = (i >> 2) & 31, nt = (i >> 7) & 1, kc = i >> 8;
            int tg = ln & 3, gd = ln >> 2;
            int krow = kc * 16 + ((e < 2) ? (2 * tg + e) : (8 + 2 * tg + (e - 2)));
            int n = nt * 8 + gd;
            p[i] = __float2bfloat16(W3[krow * 16 + n]);
        }
        if (tid < 128) b2s[tid] = b2[tid];
    }
    __syncthreads();

    // ---- per-thread point fragment geometry ----
    const int pb = blockIdx.x * 64 + warp * 16;     // warp's first point
    const int pt0 = pb + grp, pt1 = pb + 8 + grp;   // rows grp, grp+8
    const bool a0 = pt0 < npoints, aA = pt1 < npoints;

    auto ld0 = [&](int c) -> float { return a0 ? sp[pt0 * 20 + c] : 0.f; };
    auto ld1 = [&](int c) -> float { return aA ? sp[pt1 * 20 + c] : 0.f; };

    // state fragment s[8]: {t0.c0..c3, t1.c0..c3} over cols {2t,2t+1,8+2t,8+2t+1}
    float x0[8];
    x0[0] = ld0(2 * tig);     x0[1] = ld0(2 * tig + 1);
    x0[2] = ld1(2 * tig);     x0[3] = ld1(2 * tig + 1);
    x0[4] = ld0(8 + 2 * tig); x0[5] = ld0(8 + 2 * tig + 1);
    x0[6] = ld1(8 + 2 * tig); x0[7] = ld1(8 + 2 * tig + 1);

    // constant A-frag chunk1: cols 16..31 = [u0..u3, 1, 0...]
    auto lu0 = [&](int c) -> float { return (c < 20) ? ld0(c) : ((c == 20) ? 1.f : 0.f); };
    auto lu1 = [&](int c) -> float { return (c < 20) ? ld1(c) : ((c == 20) ? 1.f : 0.f); };
    uint32_t au[4];
    au[0] = pack_bf16(lu0(16 + 2 * tig), lu0(17 + 2 * tig));
    au[1] = pack_bf16(lu1(16 + 2 * tig), lu1(17 + 2 * tig));
    au[2] = 0u; au[3] = 0u;   // cols 24..31 are zero

    float b3v[4];
    b3v[0] = b3[2 * tig];     b3v[1] = b3[2 * tig + 1];
    b3v[2] = b3[8 + 2 * tig]; b3v[3] = b3[9 + 2 * tig];

    const float A21 = 0.2f;
    const float A31 = 3.f/40.f, A32 = 9.f/40.f;
    const float A41 = 44.f/45.f, A42 = -56.f/15.f, A43 = 32.f/9.f;
    const float A51 = 19372.f/6561.f, A52 = -25360.f/2187.f, A53 = 64448.f/6561.f, A54 = -212.f/729.f;
    const float A61 = 9017.f/3168.f, A62 = -355.f/33.f, A63 = 46732.f/5247.f, A64 = 49.f/176.f, A65 = -5103.f/18656.f;
    const float Bc1 = 35.f/384.f, Bc3 = 500.f/1113.f, Bc4 = 125.f/192.f, Bc5 = -2187.f/6784.f, Bc6 = 11.f/84.f;

    float k1[8], k2[8], k3[8], k4[8], k5[8], k6[8], cur[8];
    uint32_t a1[4];
#pragma unroll
    for (int i = 0; i < 8; i++) cur[i] = x0[i];

    for (int step = 0; step < 4; step++) {
        a1[0] = pack_bf16(cur[0], cur[1]); a1[1] = pack_bf16(cur[2], cur[3]);
        a1[2] = pack_bf16(cur[4], cur[5]); a1[3] = pack_bf16(cur[6], cur[7]);
        eval_f(k1, a1, au, w1f, w2f, w3f, b2s, b3v, lane, tig);
#pragma unroll
        for (int i = 0; i < 8; i++) cur[i] = x0[i] + HS * (A21 * k1[i]);

        a1[0] = pack_bf16(cur[0], cur[1]); a1[1] = pack_bf16(cur[2], cur[3]);
        a1[2] = pack_bf16(cur[4], cur[5]); a1[3] = pack_bf16(cur[6], cur[7]);
        eval_f(k2, a1, au, w1f, w2f, w3f, b2s, b3v, lane, tig);
#pragma unroll
        for (int i = 0; i < 8; i++) cur[i] = x0[i] + HS * (A31 * k1[i] + A32 * k2[i]);

        a1[0] = pack_bf16(cur[0], cur[1]); a1[1] = pack_bf16(cur[2], cur[3]);
        a1[2] = pack_bf16(cur[4], cur[5]); a1[3] = pack_bf16(cur[6], cur[7]);
        eval_f(k3, a1, au, w1f, w2f, w3f, b2s, b3v, lane, tig);
#pragma unroll
        for (int i = 0; i < 8; i++) cur[i] = x0[i] + HS * (A41 * k1[i] + A42 * k2[i] + A43 * k3[i]);

        a1[0] = pack_bf16(cur[0], cur[1]); a1[1] = pack_bf16(cur[2], cur[3]);
        a1[2] = pack_bf16(cur[4], cur[5]); a1[3] = pack_bf16(cur[6], cur[7]);
        eval_f(k4, a1, au, w1f, w2f, w3f, b2s, b3v, lane, tig);
#pragma unroll
        for (int i = 0; i < 8; i++)
            cur[i] = x0[i] + HS * (A51 * k1[i] + A52 * k2[i] + A53 * k3[i] + A54 * k4[i]);

        a1[0] = pack_bf16(cur[0], cur[1]); a1[1] = pack_bf16(cur[2], cur[3]);
        a1[2] = pack_bf16(cur[4], cur[5]); a1[3] = pack_bf16(cur[6], cur[7]);
        eval_f(k5, a1, au, w1f, w2f, w3f, b2s, b3v, lane, tig);
#pragma unroll
        for (int i = 0; i < 8; i++)
            cur[i] = x0[i] + HS * (A61 * k1[i] + A62 * k2[i] + A63 * k3[i] + A64 * k4[i] + A65 * k5[i]);

        a1[0] = pack_bf16(cur[0], cur[1]); a1[1] = pack_bf16(cur[2], cur[3]);
        a1[2] = pack_bf16(cur[4], cur[5]); a1[3] = pack_bf16(cur[6], cur[7]);
        eval_f(k6, a1, au, w1f, w2f, w3f, b2s, b3v, lane, tig);
#pragma unroll
        for (int i = 0; i < 8; i++) {
            x0[i] += HS * (Bc1 * k1[i] + Bc3 * k3[i] + Bc4 * k4[i] + Bc5 * k5[i] + Bc6 * k6[i]);
            cur[i] = x0[i];
        }
    }

    // weighted per-point states -> scratch
    if (a0) {
        float w = wp[pt0];
        *(float2*)&g_scratch[pt0 * 16 + 2 * tig]     = make_float2(w * x0[0], w * x0[1]);
        *(float2*)&g_scratch[pt0 * 16 + 8 + 2 * tig] = make_float2(w * x0[4], w * x0[5]);
    }
    if (aA) {
        float w = wp[pt1];
        *(float2*)&g_scratch[pt1 * 16 + 2 * tig]     = make_float2(w * x0[2], w * x0[3]);
        *(float2*)&g_scratch[pt1 * 16 + 8 + 2 * tig] = make_float2(w * x0[6], w * x0[7]);
    }
}

__global__ void reduce_kernel(float* __restrict__ out, int B)
{
    int t = blockIdx.x * blockDim.x + threadIdx.x;
    if (t >= B * 16) return;
    int b = t >> 4, o = t & 15;
    const float* src = g_scratch + (b * 41) * 16 + o;
    float s = 0.f;
#pragma unroll
    for (int j = 0; j < 41; j++) s += src[j * 16];
    out[t] = s;
}

extern "C" void kernel_launch(void* const* d_in, const int* in_sizes, int n_in,
                              void* d_out, int out_size)
{
    const float* sp = (const float*)d_in[0];
    const float* wp = (const float*)d_in[1];
    const float* W1 = (const float*)d_in[2];
    const float* b1 = (const float*)d_in[3];
    const float* W2 = (const float*)d_in[4];
    const float* b2 = (const float*)d_in[5];
    const float* W3 = (const float*)d_in[6];
    const float* b3 = (const float*)d_in[7];
    float* out = (float*)d_out;

    int npoints = in_sizes[0] / 20;          // B * 41
    if (npoints > 1024 * 41) npoints = 1024 * 41;
    int B = npoints / 41;

    int nblocks = (npoints + 63) / 64;       // 656 for B=1024
    integ_kernel<<<nblocks, 128>>>(sp, wp, W1, b1, W2, b2, W3, b3, npoints);

    int nthr = B * 16;
    reduce_kernel<<<(nthr + 255) / 256, 256>>>(out, B);
}